// round 17
// baseline (speedup 1.0000x reference)
#include <cuda_runtime.h>
#include <math.h>

#define N_NODES 346
#define L_SEQ   50
#define D_EMB   300
#define H_HID   300
#define G4      1200   // 4*H

// ---------------------------------------------------------------------------
// Scratch pool (static device allocation — no cudaMalloc anywhere)
// ---------------------------------------------------------------------------
constexpr size_t A256(size_t x) { return (x + 255) & ~(size_t)255; }

constexpr size_t SZ_P   = (size_t)L_SEQ * N_NODES * G4;
constexpr size_t SZ_O0  = (size_t)L_SEQ * N_NODES * 600;
constexpr size_t SZ_NG4 = (size_t)N_NODES * G4;

constexpr size_t OFF_P0F  = 0;
constexpr size_t OFF_P0B  = A256(OFF_P0F + SZ_P);
constexpr size_t OFF_O0   = A256(OFF_P0B + SZ_P);
constexpr size_t OFF_HSA  = A256(OFF_O0  + SZ_O0);
constexpr size_t OFF_HSB  = A256(OFF_HSA + SZ_NG4);
constexpr size_t OFF_CAT  = A256(OFF_HSB + SZ_NG4);
constexpr size_t OFF_WH   = A256(OFF_CAT + (size_t)N_NODES * 2400);
constexpr size_t OFF_ATT  = A256(OFF_WH  + SZ_NG4);
constexpr size_t OFF_HS1  = A256(OFF_ATT + (size_t)N_NODES * N_NODES);
constexpr size_t OFF_HS2  = A256(OFF_HS1 + SZ_NG4);
constexpr size_t OFF_Z    = A256(OFF_HS2 + SZ_NG4);
constexpr size_t OFF_HC3  = A256(OFF_Z   + (size_t)N_NODES * 4800);
constexpr size_t OFF_WHHR  = A256(OFF_HC3  + (size_t)N_NODES * 9600);
constexpr size_t OFF_WIHR0 = A256(OFF_WHHR + 4 * (size_t)G4 * H_HID);
constexpr size_t OFF_WIHR1 = A256(OFF_WIHR0 + 2 * (size_t)G4 * 300);
constexpr size_t OFF_BR    = A256(OFF_WIHR1 + 2 * (size_t)G4 * 600);
constexpr size_t OFF_BAR  = A256(OFF_BR  + 4 * (size_t)G4);
constexpr size_t OFF_U    = A256(OFF_BAR + 64);
constexpr size_t OFF_V    = A256(OFF_U   + 512);
constexpr size_t OFF_S    = A256(OFF_V   + 32);
constexpr size_t OFF_E1   = A256(OFF_S   + 1280);
constexpr size_t OFF_E2   = A256(OFF_E1  + 512);
constexpr size_t OFF_BATT = A256(OFF_E2  + 512);
constexpr size_t OFF_EA   = A256(OFF_BATT + 512);
constexpr size_t SZ_HC   = (size_t)N_NODES * 9600;
constexpr size_t OFF_FCP  = A256(OFF_EA + 2560);
constexpr size_t POOL_SZ  = A256(OFF_FCP + 8 * SZ_HC);

// scratch aliases inside FCP region (disjoint lifetimes)
constexpr size_t OFF_CSP  = OFF_FCP;            // colsum partials: 8 x 1200
constexpr size_t OFF_GATP = OFF_FCP + 16384;    // GAT split-K partials: 2 x 415200

__device__ float g_pool[POOL_SZ];

__device__ __forceinline__ float sigm_(float x) { return 1.0f / (1.0f + expf(-x)); }

// ---------------------------------------------------------------------------
// 64x64x16 fp32 GEMM core, double-buffered — GAT GEMMs
// ---------------------------------------------------------------------------
#define BM 64
#define BN 64
#define BK 16
#define SPAD 68

template<int TB>
__device__ __forceinline__ void gemm_acc64(
    int M, int N, int K,
    const float* __restrict__ A, int lda,
    const float* __restrict__ B, int ldb,
    float (*As)[BK * SPAD], float (*Bs)[BK * SPAD], float acc[4][4],
    int m0, int n0, int tid, int tx, int ty)
{
#pragma unroll
    for (int i = 0; i < 4; i++)
#pragma unroll
        for (int j = 0; j < 4; j++) acc[i][j] = 0.0f;

    const int nt = (K + BK - 1) / BK;

#pragma unroll
    for (int i = 0; i < 4; i++) {
        int idx = tid + i * 256;
        int m = idx >> 4, k = idx & 15;
        int gm = m0 + m, gk = k;
        As[0][k * SPAD + m] = (gm < M && gk < K) ? __ldg(&A[(size_t)gm * lda + gk]) : 0.0f;
    }
    if (TB) {
#pragma unroll
        for (int i = 0; i < 4; i++) {
            int idx = tid + i * 256;
            int j = idx >> 4, k = idx & 15;
            int gj = n0 + j, gk = k;
            Bs[0][k * SPAD + j] = (gj < N && gk < K) ? __ldg(&B[(size_t)gj * ldb + gk]) : 0.0f;
        }
    } else {
#pragma unroll
        for (int i = 0; i < 4; i++) {
            int idx = tid + i * 256;
            int j = idx & 63, k = idx >> 6;
            int gj = n0 + j, gk = k;
            Bs[0][k * SPAD + j] = (gj < N && gk < K) ? __ldg(&B[(size_t)gk * ldb + gj]) : 0.0f;
        }
    }
    __syncthreads();

    float ra[4], rb[4];
    for (int t = 0; t < nt; t++) {
        const int cur = t & 1;
        const bool more = (t + 1 < nt);
        if (more) {
            int k0 = (t + 1) * BK;
#pragma unroll
            for (int i = 0; i < 4; i++) {
                int idx = tid + i * 256;
                int m = idx >> 4, k = idx & 15;
                int gm = m0 + m, gk = k0 + k;
                ra[i] = (gm < M && gk < K) ? __ldg(&A[(size_t)gm * lda + gk]) : 0.0f;
            }
            if (TB) {
#pragma unroll
                for (int i = 0; i < 4; i++) {
                    int idx = tid + i * 256;
                    int j = idx >> 4, k = idx & 15;
                    int gj = n0 + j, gk = k0 + k;
                    rb[i] = (gj < N && gk < K) ? __ldg(&B[(size_t)gj * ldb + gk]) : 0.0f;
                }
            } else {
#pragma unroll
                for (int i = 0; i < 4; i++) {
                    int idx = tid + i * 256;
                    int j = idx & 63, k = idx >> 6;
                    int gj = n0 + j, gk = k0 + k;
                    rb[i] = (gj < N && gk < K) ? __ldg(&B[(size_t)gk * ldb + gj]) : 0.0f;
                }
            }
        }
#pragma unroll
        for (int kk = 0; kk < BK; kk++) {
            float4 av = *reinterpret_cast<const float4*>(&As[cur][kk * SPAD + ty * 4]);
            float4 bv = *reinterpret_cast<const float4*>(&Bs[cur][kk * SPAD + tx * 4]);
            float a[4] = {av.x, av.y, av.z, av.w};
            float b[4] = {bv.x, bv.y, bv.z, bv.w};
#pragma unroll
            for (int i = 0; i < 4; i++)
#pragma unroll
                for (int j = 0; j < 4; j++)
                    acc[i][j] += a[i] * b[j];
        }
        if (more) {
            const int nxt = cur ^ 1;
#pragma unroll
            for (int i = 0; i < 4; i++) {
                int idx = tid + i * 256;
                int m = idx >> 4, k = idx & 15;
                As[nxt][k * SPAD + m] = ra[i];
            }
            if (TB) {
#pragma unroll
                for (int i = 0; i < 4; i++) {
                    int idx = tid + i * 256;
                    int j = idx >> 4, k = idx & 15;
                    Bs[nxt][k * SPAD + j] = rb[i];
                }
            } else {
#pragma unroll
                for (int i = 0; i < 4; i++) {
                    int idx = tid + i * 256;
                    int j = idx & 63, k = idx >> 6;
                    Bs[nxt][k * SPAD + j] = rb[i];
                }
            }
            __syncthreads();
        }
    }
}

template<int TB, int EPI>
__global__ void __launch_bounds__(256) gemm_kernel(
    int M, int N, int K,
    const float* __restrict__ A, int lda,
    const float* __restrict__ B, int ldb,
    const float* __restrict__ Dm, int ldd,
    float* __restrict__ C, int ldc)
{
    __shared__ float As[2][BK * SPAD], Bs[2][BK * SPAD];
    const int m0 = blockIdx.y * BM, n0 = blockIdx.x * BN;
    const int tid = threadIdx.x, tx = tid & 15, ty = tid >> 4;
    float acc[4][4];
    gemm_acc64<TB>(M, N, K, A, lda, B, ldb, As, Bs, acc, m0, n0, tid, tx, ty);

#pragma unroll
    for (int i = 0; i < 4; i++) {
        int gm = m0 + ty * 4 + i;
        if (gm >= M) continue;
#pragma unroll
        for (int j = 0; j < 4; j++) {
            int gn = n0 + tx * 4 + j;
            if (gn >= N) continue;
            float v = acc[i][j];
            if (Dm) v += (ldd == 0) ? Dm[gn] : Dm[(size_t)gm * ldd + gn];
            if (EPI == 1) v = tanhf(v);
            if (EPI == 2) v = (v > 0.0f) ? v : expm1f(v);
            C[(size_t)gm * ldc + gn] = v;
        }
    }
}

// Split-K GEMM (TB=0): z-slice of K, partials to P[z][M*N]
__global__ void __launch_bounds__(256) gemmsk_kernel(
    int M, int N, int K2,
    const float* __restrict__ A, int lda,
    const float* __restrict__ B, int ldb,
    float* __restrict__ P)
{
    __shared__ float As[2][BK * SPAD], Bs[2][BK * SPAD];
    const int z = blockIdx.z;
    const float* Az = A + (size_t)z * K2;
    const float* Bz = B + (size_t)z * K2 * ldb;
    const int m0 = blockIdx.y * BM, n0 = blockIdx.x * BN;
    const int tid = threadIdx.x, tx = tid & 15, ty = tid >> 4;
    float acc[4][4];
    gemm_acc64<0>(M, N, K2, Az, lda, Bz, ldb, As, Bs, acc, m0, n0, tid, tx, ty);

    float* C = P + (size_t)z * M * N;
#pragma unroll
    for (int i = 0; i < 4; i++) {
        int gm = m0 + ty * 4 + i;
        if (gm >= M) continue;
#pragma unroll
        for (int j = 0; j < 4; j++) {
            int gn = n0 + tx * 4 + j;
            if (gn >= N) continue;
            C[(size_t)gm * N + gn] = acc[i][j];
        }
    }
}

__global__ void add2_kernel(const float* __restrict__ P, float* __restrict__ out, int n)
{
    int i = blockIdx.x * blockDim.x + threadIdx.x;
    if (i < n) out[i] = P[i] + P[(size_t)n + i];
}

// ---------------------------------------------------------------------------
// Dual projection GEMM (fwd+bwd via blockIdx.z), 128x128x8, float4 LDG.
// GATHER=1: A row gm is emb[tok[n*L + t]] with t=gm/N_NODES, n=gm%N_NODES.
// ---------------------------------------------------------------------------
#define XBM 128
#define XBN 128
#define XBK 8
#define XPAD 132

__device__ __forceinline__ float4 ldrow4(const float* __restrict__ row, int K, int gk)
{
    float4 v = make_float4(0.f, 0.f, 0.f, 0.f);
    if (row) {
        if (gk + 3 < K) v = *reinterpret_cast<const float4*>(&row[gk]);
        else {
            if (gk < K)     v.x = row[gk];
            if (gk + 1 < K) v.y = row[gk + 1];
            if (gk + 2 < K) v.z = row[gk + 2];
        }
    }
    return v;
}

template<int GATHER>
__global__ void __launch_bounds__(256) proj_dual_kernel(
    int M, int K,
    const float* __restrict__ A,
    const int* __restrict__ tok, const float* __restrict__ emb,
    const float* __restrict__ B0, const float* __restrict__ B1,
    const float* __restrict__ bias0, const float* __restrict__ bias1,
    float* __restrict__ C0, float* __restrict__ C1)
{
    __shared__ float As[2][XBK * XPAD], Bs[2][XBK * XPAD];
    const float* B    = blockIdx.z ? B1 : B0;
    const float* bias = blockIdx.z ? bias1 : bias0;
    float* C          = blockIdx.z ? C1 : C0;

    const int m0 = blockIdx.y * XBM, n0 = blockIdx.x * XBN;
    const int tid = threadIdx.x, tx = tid & 15, ty = tid >> 4;
    const int lr = tid >> 1, lk = (tid & 1) * 4;

    // per-thread fixed source rows
    const float* arow = nullptr;
    {
        int gm = m0 + lr;
        if (gm < M) {
            if (GATHER) {
                int t = gm / N_NODES, n = gm - t * N_NODES;
                arow = emb + (size_t)tok[n * L_SEQ + t] * D_EMB;
            } else {
                arow = A + (size_t)gm * K;
            }
        }
    }
    const float* brow = (n0 + lr < G4) ? (B + (size_t)(n0 + lr) * K) : nullptr;

    float acc[8][8];
#pragma unroll
    for (int i = 0; i < 8; i++)
#pragma unroll
        for (int j = 0; j < 8; j++) acc[i][j] = 0.0f;

    const int nt = (K + XBK - 1) / XBK;

    {
        float4 va = ldrow4(arow, K, lk);
        float4 vb = ldrow4(brow, K, lk);
        As[0][(lk + 0) * XPAD + lr] = va.x;
        As[0][(lk + 1) * XPAD + lr] = va.y;
        As[0][(lk + 2) * XPAD + lr] = va.z;
        As[0][(lk + 3) * XPAD + lr] = va.w;
        Bs[0][(lk + 0) * XPAD + lr] = vb.x;
        Bs[0][(lk + 1) * XPAD + lr] = vb.y;
        Bs[0][(lk + 2) * XPAD + lr] = vb.z;
        Bs[0][(lk + 3) * XPAD + lr] = vb.w;
    }
    __syncthreads();

    float4 ra, rb;
    for (int t = 0; t < nt; t++) {
        const int cur = t & 1;
        const bool more = (t + 1 < nt);
        if (more) {
            int k0 = (t + 1) * XBK;
            ra = ldrow4(arow, K, k0 + lk);
            rb = ldrow4(brow, K, k0 + lk);
        }
#pragma unroll
        for (int kk = 0; kk < XBK; kk++) {
            float a[8], b[8];
            float4 a0 = *reinterpret_cast<const float4*>(&As[cur][kk * XPAD + ty * 8]);
            float4 a1 = *reinterpret_cast<const float4*>(&As[cur][kk * XPAD + ty * 8 + 4]);
            float4 b0 = *reinterpret_cast<const float4*>(&Bs[cur][kk * XPAD + tx * 8]);
            float4 b1 = *reinterpret_cast<const float4*>(&Bs[cur][kk * XPAD + tx * 8 + 4]);
            a[0]=a0.x; a[1]=a0.y; a[2]=a0.z; a[3]=a0.w;
            a[4]=a1.x; a[5]=a1.y; a[6]=a1.z; a[7]=a1.w;
            b[0]=b0.x; b[1]=b0.y; b[2]=b0.z; b[3]=b0.w;
            b[4]=b1.x; b[5]=b1.y; b[6]=b1.z; b[7]=b1.w;
#pragma unroll
            for (int i = 0; i < 8; i++)
#pragma unroll
                for (int j = 0; j < 8; j++)
                    acc[i][j] += a[i] * b[j];
        }
        if (more) {
            const int nxt = cur ^ 1;
            As[nxt][(lk + 0) * XPAD + lr] = ra.x;
            As[nxt][(lk + 1) * XPAD + lr] = ra.y;
            As[nxt][(lk + 2) * XPAD + lr] = ra.z;
            As[nxt][(lk + 3) * XPAD + lr] = ra.w;
            Bs[nxt][(lk + 0) * XPAD + lr] = rb.x;
            Bs[nxt][(lk + 1) * XPAD + lr] = rb.y;
            Bs[nxt][(lk + 2) * XPAD + lr] = rb.z;
            Bs[nxt][(lk + 3) * XPAD + lr] = rb.w;
            __syncthreads();
        }
    }

#pragma unroll
    for (int i = 0; i < 8; i++) {
        int gm = m0 + ty * 8 + i;
        if (gm >= M) continue;
#pragma unroll
        for (int j = 0; j < 8; j++) {
            int gn = n0 + tx * 8 + j;
            if (gn >= G4) continue;
            C[(size_t)gm * G4 + gn] = acc[i][j] + bias[gn];
        }
    }
}

// ---------------------------------------------------------------------------
// FC1 split-K: partial GEMM (K chunk 600 per z) + reduction with tanh.
// ---------------------------------------------------------------------------
#define FC1_KS 8
#define FC1_KC 600

__global__ void __launch_bounds__(256) fc1_partial_kernel(
    const float* __restrict__ A,     // Z, lda 4800
    const float* __restrict__ B,     // FC1, ldb 9600
    float* __restrict__ P)
{
    __shared__ float As[2][XBK * XPAD], Bs[2][XBK * XPAD];
    const int M = N_NODES;
    const int lda = 4800, ldb = 9600;
    const int kbase = blockIdx.z * FC1_KC;
    const int m0 = blockIdx.y * XBM, n0 = blockIdx.x * XBN;
    const int tid = threadIdx.x, tx = tid & 15, ty = tid >> 4;
    const int lr = tid >> 1, lk = (tid & 1) * 4;
    const int bk = tid >> 5, bj = (tid & 31) * 4;
    float* C = P + (size_t)blockIdx.z * SZ_HC;

    float acc[8][8];
#pragma unroll
    for (int i = 0; i < 8; i++)
#pragma unroll
        for (int j = 0; j < 8; j++) acc[i][j] = 0.0f;

    const int nt = FC1_KC / XBK;   // 75

    {
        int gm = m0 + lr;
        float4 va = make_float4(0.f, 0.f, 0.f, 0.f);
        if (gm < M) va = *reinterpret_cast<const float4*>(&A[(size_t)gm * lda + kbase + lk]);
        As[0][(lk + 0) * XPAD + lr] = va.x;
        As[0][(lk + 1) * XPAD + lr] = va.y;
        As[0][(lk + 2) * XPAD + lr] = va.z;
        As[0][(lk + 3) * XPAD + lr] = va.w;
        float4 vb = *reinterpret_cast<const float4*>(&B[(size_t)(kbase + bk) * ldb + n0 + bj]);
        *reinterpret_cast<float4*>(&Bs[0][bk * XPAD + bj]) = vb;
    }
    __syncthreads();

    float4 ra, rb;
    for (int t = 0; t < nt; t++) {
        const int cur = t & 1;
        const bool more = (t + 1 < nt);
        if (more) {
            int k0 = kbase + (t + 1) * XBK;
            int gm = m0 + lr;
            ra = make_float4(0.f, 0.f, 0.f, 0.f);
            if (gm < M) ra = *reinterpret_cast<const float4*>(&A[(size_t)gm * lda + k0 + lk]);
            rb = *reinterpret_cast<const float4*>(&B[(size_t)(k0 + bk) * ldb + n0 + bj]);
        }
#pragma unroll
        for (int kk = 0; kk < XBK; kk++) {
            float a[8], b[8];
            float4 a0 = *reinterpret_cast<const float4*>(&As[cur][kk * XPAD + ty * 8]);
            float4 a1 = *reinterpret_cast<const float4*>(&As[cur][kk * XPAD + ty * 8 + 4]);
            float4 b0 = *reinterpret_cast<const float4*>(&Bs[cur][kk * XPAD + tx * 8]);
            float4 b1 = *reinterpret_cast<const float4*>(&Bs[cur][kk * XPAD + tx * 8 + 4]);
            a[0]=a0.x; a[1]=a0.y; a[2]=a0.z; a[3]=a0.w;
            a[4]=a1.x; a[5]=a1.y; a[6]=a1.z; a[7]=a1.w;
            b[0]=b0.x; b[1]=b0.y; b[2]=b0.z; b[3]=b0.w;
            b[4]=b1.x; b[5]=b1.y; b[6]=b1.z; b[7]=b1.w;
#pragma unroll
            for (int i = 0; i < 8; i++)
#pragma unroll
                for (int j = 0; j < 8; j++)
                    acc[i][j] += a[i] * b[j];
        }
        if (more) {
            const int nxt = cur ^ 1;
            As[nxt][(lk + 0) * XPAD + lr] = ra.x;
            As[nxt][(lk + 1) * XPAD + lr] = ra.y;
            As[nxt][(lk + 2) * XPAD + lr] = ra.z;
            As[nxt][(lk + 3) * XPAD + lr] = ra.w;
            *reinterpret_cast<float4*>(&Bs[nxt][bk * XPAD + bj]) = rb;
            __syncthreads();
        }
    }

#pragma unroll
    for (int i = 0; i < 8; i++) {
        int gm = m0 + ty * 8 + i;
        if (gm >= M) continue;
#pragma unroll
        for (int j = 0; j < 8; j++) {
            int gn = n0 + tx * 8 + j;
            C[(size_t)gm * 9600 + gn] = acc[i][j];
        }
    }
}

__global__ void fc1_reduce_kernel(const float* __restrict__ P, float* __restrict__ out)
{
    size_t idx = (size_t)blockIdx.x * blockDim.x + threadIdx.x;
    if (idx >= SZ_HC) return;
    float s = 0.0f;
#pragma unroll
    for (int z = 0; z < FC1_KS; z++) s += P[(size_t)z * SZ_HC + idx];
    out[idx] = tanhf(s);
}

// ---------------------------------------------------------------------------
// Persistent LSTM scan (R13 winner, unchanged)
// ---------------------------------------------------------------------------
#define LBN 48
#define LSPD 52
#define LTHREADS 192
constexpr int LSTM_GX = G4 / LBN;                  // 25
constexpr int LSTM_GY = (N_NODES + BM - 1) / BM;   // 6
constexpr unsigned LSTM_BLOCKS = LSTM_GX * LSTM_GY * 2;  // 300
constexpr int BS_ROWS = 304;
constexpr size_t SMEM_SCAN = (size_t)(BS_ROWS * LSPD + 2 * BK * SPAD) * 4;

__global__ void __launch_bounds__(LTHREADS) lstm_scan_kernel(
    float* __restrict__ hsA, float* __restrict__ hsB,
    int hcol_f, int hcol_b,
    const float* __restrict__ Whh_rf, const float* __restrict__ Whh_rb,
    const float* __restrict__ Pf, const float* __restrict__ Pb,
    float* __restrict__ outbuf,
    unsigned* __restrict__ bar)
{
    extern __shared__ float smem[];
    float* Bres = smem;
    float* As   = smem + BS_ROWS * LSPD;

    const int z = blockIdx.z;
    const int hcol = z ? hcol_b : hcol_f;
    const float* Bw = z ? Whh_rb : Whh_rf;
    const float* Pbase = z ? Pb : Pf;

    const int m0 = blockIdx.y * BM, n0 = blockIdx.x * LBN;
    const int tid = threadIdx.x;
    const int tx = tid % 12, ty = tid / 12;

    for (int idx = tid; idx < LBN * BS_ROWS; idx += LTHREADS) {
        int j = idx / BS_ROWS, k = idx % BS_ROWS;
        int gj = n0 + j;
        Bres[k * LSPD + j] = (gj < G4 && k < H_HID) ? __ldg(&Bw[(size_t)gj * H_HID + k]) : 0.0f;
    }

    const int r0 = n0 + tx * 4;
    const int ju = r0 >> 2;
    float c_reg[4] = {0.0f, 0.0f, 0.0f, 0.0f};

    __syncthreads();

    const int nt = (H_HID + BK - 1) / BK;

    for (int t = 0; t < L_SEQ; t++) {
        const float* hin  = (t & 1) ? hsB : hsA;
        float*       hout = (t & 1) ? hsA : hsB;
        const float* A = hin + hcol;

        for (int idx = tid; idx < BM * BK; idx += LTHREADS) {
            int m = idx >> 4, k = idx & 15;
            int gm = m0 + m;
            As[k * SPAD + m] = (gm < N_NODES) ? __ldg(&A[(size_t)gm * G4 + k]) : 0.0f;
        }
        __syncthreads();

        float acc[4][4];
#pragma unroll
        for (int i = 0; i < 4; i++)
#pragma unroll
            for (int j = 0; j < 4; j++) acc[i][j] = 0.0f;

        float ra[6];
        for (int kt = 0; kt < nt; kt++) {
            const int cur = kt & 1;
            const bool more = (kt + 1 < nt);
            if (more) {
                int k0 = (kt + 1) * BK;
#pragma unroll
                for (int i = 0; i < 6; i++) {
                    int idx = tid + i * LTHREADS;
                    if (idx < BM * BK) {
                        int m = idx >> 4, k = idx & 15;
                        int gm = m0 + m, gk = k0 + k;
                        ra[i] = (gm < N_NODES && gk < H_HID) ? __ldg(&A[(size_t)gm * G4 + gk]) : 0.0f;
                    }
                }
            }
#pragma unroll
            for (int kk = 0; kk < BK; kk++) {
                float4 av = *reinterpret_cast<const float4*>(&As[cur * (BK * SPAD) + kk * SPAD + ty * 4]);
                float4 bv = *reinterpret_cast<const float4*>(&Bres[(kt * BK + kk) * LSPD + tx * 4]);
                float a[4] = {av.x, av.y, av.z, av.w};
                float b[4] = {bv.x, bv.y, bv.z, bv.w};
#pragma unroll
                for (int i = 0; i < 4; i++)
#pragma unroll
                    for (int j = 0; j < 4; j++)
                        acc[i][j] += a[i] * b[j];
            }
            if (more) {
                const int nxt = cur ^ 1;
#pragma unroll
                for (int i = 0; i < 6; i++) {
                    int idx = tid + i * LTHREADS;
                    if (idx < BM * BK) {
                        int m = idx >> 4, k = idx & 15;
                        As[nxt * (BK * SPAD) + k * SPAD + m] = ra[i];
                    }
                }
                __syncthreads();
            }
        }

        {
            const size_t toff = (size_t)(z ? (L_SEQ - 1 - t) : t) * N_NODES * G4;
            const float* P = Pbase + toff;
#pragma unroll
            for (int i = 0; i < 4; i++) {
                int gm = m0 + ty * 4 + i;
                if (gm >= N_NODES) continue;
                float4 p = *reinterpret_cast<const float4*>(P + (size_t)gm * G4 + r0);
                float gi = acc[i][0] + p.x;
                float gf = acc[i][1] + p.y;
                float gg = acc[i][2] + p.z;
                float go = acc[i][3] + p.w;
                float cn = sigm_(gf) * c_reg[i] + sigm_(gi) * tanhf(gg);
                float h  = sigm_(go) * tanhf(cn);
                c_reg[i] = cn;
                hout[(size_t)gm * G4 + hcol + ju] = h;
                if (outbuf) {
                    int tt = z ? (L_SEQ - 1 - t) : t;
                    outbuf[(size_t)tt * N_NODES * 600 + (size_t)gm * 600 + z * H_HID + ju] = h;
                }
            }
        }

        if (t + 1 < L_SEQ) {
            __threadfence();
            __syncthreads();
            if (tid == 0) {
                atomicAdd(bar, 1u);
                const unsigned target = LSTM_BLOCKS * (unsigned)(t + 1);
                const volatile unsigned* vb = bar;
                while (*vb < target) __nanosleep(64);
                __threadfence();
            }
            __syncthreads();
        }
    }
}

// ---------------------------------------------------------------------------
// prep: weight reorders + bias reorders + HSA zero + barrier counters
// ---------------------------------------------------------------------------
constexpr size_t PREP_W3 = (size_t)G4 * 300;
constexpr size_t PREP_W6 = (size_t)G4 * 600;
constexpr size_t PREP_B0 = 6 * PREP_W3;
constexpr size_t PREP_B1 = PREP_B0 + 2 * PREP_W6;
constexpr size_t PREP_B2 = PREP_B1 + 4 * (size_t)G4;
constexpr size_t PREP_TOTAL = PREP_B2 + SZ_NG4;

__device__ __forceinline__ void reo_(const float* in, float* out, size_t idx, int K) {
    int r = (int)(idx / K), k = (int)(idx % K);
    int j = r >> 2, g = r & 3;
    out[(size_t)r * K + k] = in[(size_t)(g * H_HID + j) * K + k];
}

__global__ void prep_kernel(
    const float* __restrict__ Wih_l0f, const float* __restrict__ Wih_l0b,
    const float* __restrict__ Whh_l0f, const float* __restrict__ Whh_l0b,
    const float* __restrict__ Whh_l1f, const float* __restrict__ Whh_l1b,
    const float* __restrict__ Wih_l1f, const float* __restrict__ Wih_l1b,
    const float* __restrict__ b_l0f, const float* __restrict__ b_l0b,
    const float* __restrict__ b_l1f, const float* __restrict__ b_l1b,
    float* __restrict__ pool)
{
    size_t i = (size_t)blockIdx.x * blockDim.x + threadIdx.x;
    if (i == 0) {
        ((unsigned*)(pool + OFF_BAR))[0] = 0u;
        ((unsigned*)(pool + OFF_BAR))[1] = 0u;
    }
    if (i >= PREP_TOTAL) return;

    float* WIHR0 = pool + OFF_WIHR0;
    float* WIHR1 = pool + OFF_WIHR1;
    float* WHHR  = pool + OFF_WHHR;
    float* BR    = pool + OFF_BR;

    if (i < PREP_B0) {
        int seg = (int)(i / PREP_W3);
        size_t l = i % PREP_W3;
        switch (seg) {
            case 0: reo_(Wih_l0f, WIHR0 + 0 * PREP_W3, l, 300); break;
            case 1: reo_(Wih_l0b, WIHR0 + 1 * PREP_W3, l, 300); break;
            case 2: reo_(Whh_l0f, WHHR + 0 * PREP_W3, l, 300); break;
            case 3: reo_(Whh_l0b, WHHR + 1 * PREP_W3, l, 300); break;
            case 4: reo_(Whh_l1f, WHHR + 2 * PREP_W3, l, 300); break;
            default: reo_(Whh_l1b, WHHR + 3 * PREP_W3, l, 300); break;
        }
    } else if (i < PREP_B1) {
        size_t l = i - PREP_B0;
        if (l < PREP_W6) reo_(Wih_l1f, WIHR1 + 0 * PREP_W6, l, 600);
        else             reo_(Wih_l1b, WIHR1 + 1 * PREP_W6, l - PREP_W6, 600);
    } else if (i < PREP_B2) {
        size_t l = i - PREP_B1;
        int which = (int)(l / G4);
        int r = (int)(l % G4);
        int j = r >> 2, g = r & 3;
        const float* src = (which == 0) ? b_l0f : (which == 1) ? b_l0b : (which == 2) ? b_l1f : b_l1b;
        BR[(size_t)which * G4 + r] = src[g * H_HID + j];
    } else {
        pool[OFF_HSA + (i - PREP_B2)] = 0.0f;
    }
}

// out[row] = epi( dot(A[row,:K], w) )
template<int EPI>
__global__ void rows_dot_kernel(const float* __restrict__ A, int lda,
                                const float* __restrict__ w, int K,
                                float* __restrict__ out)
{
    __shared__ float red[8];
    const float* a = A + (size_t)blockIdx.x * lda;
    float s = 0.0f;
    for (int k = threadIdx.x; k < K; k += blockDim.x) s += a[k] * w[k];
#pragma unroll
    for (int o = 16; o > 0; o >>= 1) s += __shfl_down_sync(0xffffffffu, s, o);
    if ((threadIdx.x & 31) == 0) red[threadIdx.x >> 5] = s;
    __syncthreads();
    if (threadIdx.x == 0) {
        float t = 0.0f;
        int nw = blockDim.x >> 5;
        for (int i = 0; i < nw; i++) t += red[i];
        if (EPI == 1) t = tanhf(t);
        out[blockIdx.x] = t;
    }
}

__global__ void rows_dot2_kernel(const float* __restrict__ A, int lda,
                                 const float* __restrict__ w1,
                                 const float* __restrict__ w2, int K,
                                 float* __restrict__ out1, float* __restrict__ out2)
{
    __shared__ float red1[8], red2[8];
    const float* a = A + (size_t)blockIdx.x * lda;
    float s1 = 0.0f, s2 = 0.0f;
    for (int k = threadIdx.x; k < K; k += blockDim.x) {
        float v = a[k];
        s1 += v * w1[k];
        s2 += v * w2[k];
    }
#pragma unroll
    for (int o = 16; o > 0; o >>= 1) {
        s1 += __shfl_down_sync(0xffffffffu, s1, o);
        s2 += __shfl_down_sync(0xffffffffu, s2, o);
    }
    if ((threadIdx.x & 31) == 0) { red1[threadIdx.x >> 5] = s1; red2[threadIdx.x >> 5] = s2; }
    __syncthreads();
    if (threadIdx.x == 0) {
        float t1 = 0.0f, t2 = 0.0f;
        int nw = blockDim.x >> 5;
        for (int i = 0; i < nw; i++) { t1 += red1[i]; t2 += red2[i]; }
        out1[blockIdx.x] = t1;
        out2[blockIdx.x] = t2;
    }
}

// ---------------------------------------------------------------------------
// Two-stage colsum: partials over 8 row-chunks, then deterministic reduce.
// ---------------------------------------------------------------------------
#define CSCH 8

__global__ void colsum_part_kernel(const float* __restrict__ A, int lda, int rows,
                                   const float* __restrict__ w,
                                   float* __restrict__ part, int ncols)
{
    int j = blockIdx.x * blockDim.x + threadIdx.x;
    int c = blockIdx.y;
    if (j >= ncols) return;
    int r0 = (rows * c) / CSCH, r1 = (rows * (c + 1)) / CSCH;
    float s = 0.0f;
    for (int n = r0; n < r1; n++) {
        float v = A[(size_t)n * lda + j];
        s += w ? w[n] * v : v;
    }
    part[(size_t)c * ncols + j] = s;
}

__global__ void colsum_red_kernel(const float* __restrict__ part, float scale,
                                  float* __restrict__ out, int ncols)
{
    int j = blockIdx.x * blockDim.x + threadIdx.x;
    if (j >= ncols) return;
    float s = 0.0f;
#pragma unroll
    for (int c = 0; c < CSCH; c++) s += part[(size_t)c * ncols + j];
    out[j] = s * scale;
}

__global__ void gate_cat_kernel(const float* __restrict__ h,
                                const float* __restrict__ u,
                                const float* __restrict__ vsc,
                                const float* __restrict__ s,
                                float* __restrict__ cat)
{
    int idx = blockIdx.x * blockDim.x + threadIdx.x;
    if (idx >= N_NODES * G4) return;
    int n = idx / G4, j = idx % G4;
    float hv = h[(size_t)n * G4 + j];
    float h0 = h[j];
    float val;
    if (n == 0) {
        val = h0;
    } else {
        float g = sigm_(u[n] + vsc[0]);
        val = g * s[j] + (1.0f - g) * ((float)(N_NODES - 1) * h0);
    }
    cat[(size_t)n * 2400 + j] = hv;
    cat[(size_t)n * 2400 + 1200 + j] = val;
}

__global__ void att_softmax_kernel(const float* __restrict__ e1,
                                   const float* __restrict__ e2,
                                   const int* __restrict__ adj,
                                   float* __restrict__ att)
{
    __shared__ float warpred[4];
    __shared__ float s_max, s_sum;
    int i = blockIdx.x;
    float ei = e1[i];

    float mx = -3.4e38f;
    for (int j = threadIdx.x; j < N_NODES; j += blockDim.x) {
        float v = ei + e2[j];
        v = (v > 0.0f) ? v : 0.01f * v;
        if (adj[(size_t)i * N_NODES + j] <= 0) v = -9.0e15f;
        mx = fmaxf(mx, v);
    }
#pragma unroll
    for (int o = 16; o > 0; o >>= 1) mx = fmaxf(mx, __shfl_down_sync(0xffffffffu, mx, o));
    if ((threadIdx.x & 31) == 0) warpred[threadIdx.x >> 5] = mx;
    __syncthreads();
    if (threadIdx.x == 0) {
        float m2 = warpred[0];
        int nw = blockDim.x >> 5;
        for (int k = 1; k < nw; k++) m2 = fmaxf(m2, warpred[k]);
        s_max = m2;
    }
    __syncthreads();
    float smax = s_max;

    float sum = 0.0f;
    for (int j = threadIdx.x; j < N_NODES; j += blockDim.x) {
        float v = ei + e2[j];
        v = (v > 0.0f) ? v : 0.01f * v;
        if (adj[(size_t)i * N_NODES + j] <= 0) v = -9.0e15f;
        sum += expf(v - smax);
    }
#pragma unroll
    for (int o = 16; o > 0; o >>= 1) sum += __shfl_down_sync(0xffffffffu, sum, o);
    if ((threadIdx.x & 31) == 0) warpred[threadIdx.x >> 5] = sum;
    __syncthreads();
    if (threadIdx.x == 0) {
        float t = 0.0f;
        int nw = blockDim.x >> 5;
        for (int k = 0; k < nw; k++) t += warpred[k];
        s_sum = t;
    }
    __syncthreads();
    float inv = 1.0f / s_sum;

    for (int j = threadIdx.x; j < N_NODES; j += blockDim.x) {
        float v = ei + e2[j];
        v = (v > 0.0f) ? v : 0.01f * v;
        if (adj[(size_t)i * N_NODES + j] <= 0) v = -9.0e15f;
        att[(size_t)i * N_NODES + j] = expf(v - smax) * inv;
    }
}

__global__ void zassemble_kernel(const float* __restrict__ h2, float* __restrict__ Z)
{
    int idx = blockIdx.x * blockDim.x + threadIdx.x;
    if (idx >= N_NODES * G4) return;
    int n = idx / G4, j = idx % G4;
    float a = h2[j];
    float b = h2[(size_t)n * G4 + j];
    size_t base = (size_t)n * 4800;
    Z[base + j]        = a;
    Z[base + 1200 + j] = b;
    Z[base + 2400 + j] = a * b;
    Z[base + 3600 + j] = a - b;
}

__global__ void final_kernel(const float* __restrict__ ea,
                             const float* __restrict__ Wlin,
                             const float* __restrict__ blin,
                             float* __restrict__ out)
{
    __shared__ float r0[8], r1[8];
    float s0 = 0.0f, s1 = 0.0f;
    for (int j = threadIdx.x; j < 2400; j += blockDim.x) {
        float e = ea[j];
        s0 += e * Wlin[j];
        s1 += e * Wlin[2400 + j];
    }
#pragma unroll
    for (int o = 16; o > 0; o >>= 1) {
        s0 += __shfl_down_sync(0xffffffffu, s0, o);
        s1 += __shfl_down_sync(0xffffffffu, s1, o);
    }
    if ((threadIdx.x & 31) == 0) { r0[threadIdx.x >> 5] = s0; r1[threadIdx.x >> 5] = s1; }
    __syncthreads();
    if (threadIdx.x == 0) {
        float l0 = 0.0f, l1 = 0.0f;
        int nw = blockDim.x >> 5;
        for (int i = 0; i < nw; i++) { l0 += r0[i]; l1 += r1[i]; }
        l0 += blin[0]; l1 += blin[1];
        float m = fmaxf(l0, l1);
        float e0 = expf(l0 - m), e1v = expf(l1 - m);
        float inv = 1.0f / (e0 + e1v);
        out[0] = e0 * inv;
        out[1] = e1v * inv;
    }
}

// ---------------------------------------------------------------------------
// Host orchestration
// ---------------------------------------------------------------------------
static inline dim3 grid64(int M, int N)  { return dim3((N + BN - 1) / BN, (M + BM - 1) / BM); }

static void run_gate_gat(const float* h_in, float* h_out,
                         const float* gate_W, const float* gate_U,
                         const float* W_gat, const float* a_gat,
                         const int* adj, float* pool)
{
    float* U   = pool + OFF_U;
    float* Vb  = pool + OFF_V;
    float* S   = pool + OFF_S;
    float* CAT = pool + OFF_CAT;
    float* WHp = pool + OFF_WH;
    float* E1  = pool + OFF_E1;
    float* E2  = pool + OFF_E2;
    float* ATT = pool + OFF_ATT;
    float* CSP  = pool + OFF_CSP;
    float* GATP = pool + OFF_GATP;

    rows_dot_kernel<0><<<N_NODES, 256>>>(h_in, G4, gate_W, G4, U);
    rows_dot_kernel<0><<<1, 256>>>(h_in, G4, gate_U, G4, Vb);
    {
        dim3 g((G4 + 255) / 256, CSCH);
        colsum_part_kernel<<<g, 256>>>(h_in + G4, G4, N_NODES - 1, nullptr, CSP, G4);
        colsum_red_kernel<<<(G4 + 255) / 256, 256>>>(CSP, 1.0f, S, G4);
    }
    gate_cat_kernel<<<(N_NODES * G4 + 255) / 256, 256>>>(h_in, U, Vb, S, CAT);

    // W_gat GEMM split-K (K=2400 -> 2x1200), partials + reduce
    {
        dim3 g = grid64(N_NODES, G4); g.z = 2;
        gemmsk_kernel<<<g, 256>>>(N_NODES, G4, 1200, CAT, 2400, W_gat, G4, GATP);
        add2_kernel<<<((int)SZ_NG4 + 255) / 256, 256>>>(GATP, WHp, (int)SZ_NG4);
    }
    rows_dot2_kernel<<<N_NODES, 256>>>(WHp, G4, a_gat, a_gat + G4, G4, E1, E2);
    att_softmax_kernel<<<N_NODES, 128>>>(E1, E2, adj, ATT);
    gemm_kernel<0, 2><<<grid64(N_NODES, G4), 256>>>(
        N_NODES, G4, N_NODES, ATT, N_NODES, WHp, G4, nullptr, 0, h_out, G4);
}

extern "C" void kernel_launch(void* const* d_in, const int* in_sizes, int n_in,
                              void* d_out, int out_size)
{
    (void)in_sizes; (void)n_in; (void)out_size;

    float* pool = nullptr;
    cudaGetSymbolAddress((void**)&pool, g_pool);

    static bool attr_done = false;
    if (!attr_done) {
        cudaFuncSetAttribute(lstm_scan_kernel,
                             cudaFuncAttributeMaxDynamicSharedMemorySize, (int)SMEM_SCAN);
        attr_done = true;
    }

    const int*   tokens  = (const int*)d_in[0];
    const int*   adj     = (const int*)d_in[1];
    const float* emb     = (const float*)d_in[2];
    const float* Wih_l0f = (const float*)d_in[3];
    const float* Whh_l0f = (const float*)d_in[4];
    const float* b_l0f   = (const float*)d_in[5];
    const float* Wih_l0b = (const float*)d_in[6];
    const float* Whh_l0b = (const float*)d_in[7];
    const float* b_l0b   = (const float*)d_in[8];
    const float* Wih_l1f = (const float*)d_in[9];
    const float* Whh_l1f = (const float*)d_in[10];
    const float* b_l1f   = (const float*)d_in[11];
    const float* Wih_l1b = (const float*)d_in[12];
    const float* Whh_l1b = (const float*)d_in[13];
    const float* b_l1b   = (const float*)d_in[14];
    const float* W_gat   = (const float*)d_in[15];
    const float* a_gat   = (const float*)d_in[16];
    const float* gate_W  = (const float*)d_in[17];
    const float* gate_U  = (const float*)d_in[18];
    const float* FC1     = (const float*)d_in[19];
    const float* FC2     = (const float*)d_in[20];
    const float* Wlin    = (const float*)d_in[21];
    const float* blin    = (const float*)d_in[22];
    float* out = (float*)d_out;

    float* PF   = pool + OFF_P0F;
    float* PB   = pool + OFF_P0B;
    float* O0   = pool + OFF_O0;
    float* HSA  = pool + OFF_HSA;
    float* HSB  = pool + OFF_HSB;
    float* HS1  = pool + OFF_HS1;
    float* HS2  = pool + OFF_HS2;
    float* Z    = pool + OFF_Z;
    float* HC3  = pool + OFF_HC3;
    float* WHHR  = pool + OFF_WHHR;
    float* WIHR0 = pool + OFF_WIHR0;
    float* WIHR1 = pool + OFF_WIHR1;
    float* BR    = pool + OFF_BR;
    float* FCP   = pool + OFF_FCP;
    float* CSP   = pool + OFF_CSP;
    unsigned* BARC = (unsigned*)(pool + OFF_BAR);
    float* BATT = pool + OFF_BATT;
    float* EA   = pool + OFF_EA;

    const int LN = L_SEQ * N_NODES;   // 17300
    const size_t W3 = PREP_W3, W6 = PREP_W6;

    // launch 0: prep
    prep_kernel<<<(int)((PREP_TOTAL + 255) / 256), 256>>>(
        Wih_l0f, Wih_l0b, Whh_l0f, Whh_l0b, Whh_l1f, Whh_l1b,
        Wih_l1f, Wih_l1b, b_l0f, b_l0b, b_l1f, b_l1b, pool);

    // launch 1: layer-0 projections with fused embedding gather
    {
        dim3 grid((G4 + XBN - 1) / XBN, (LN + XBM - 1) / XBM, 2);
        proj_dual_kernel<1><<<grid, 256>>>(
            LN, D_EMB, nullptr, tokens, emb,
            WIHR0 + 0 * W3, WIHR0 + 1 * W3,
            BR + 0 * G4, BR + 1 * G4, PF, PB);
    }

    // launch 2: layer-0 persistent scan
    {
        dim3 grid(LSTM_GX, LSTM_GY, 2);
        lstm_scan_kernel<<<grid, LTHREADS, SMEM_SCAN>>>(
            HSA, HSB, 0, 300,
            WHHR + 0 * W3, WHHR + 1 * W3,
            PF, PB, O0, BARC + 0);
    }

    // launch 3: layer-1 projections
    {
        dim3 grid((G4 + XBN - 1) / XBN, (LN + XBM - 1) / XBM, 2);
        proj_dual_kernel<0><<<grid, 256>>>(
            LN, 600, O0, nullptr, nullptr,
            WIHR1 + 0 * W6, WIHR1 + 1 * W6,
            BR + 2 * G4, BR + 3 * G4, PF, PB);
    }

    // launch 4: layer-1 persistent scan
    {
        dim3 grid(LSTM_GX, LSTM_GY, 2);
        lstm_scan_kernel<<<grid, LTHREADS, SMEM_SCAN>>>(
            HSA, HSB, 600, 900,
            WHHR + 2 * W3, WHHR + 3 * W3,
            PF, PB, nullptr, BARC + 1);
    }
    // L_SEQ=50 (even): final h for both layers lands in HSA.

    // two gate+GAT stages
    run_gate_gat(HSA, HS1, gate_W, gate_U, W_gat, a_gat, adj, pool);
    run_gate_gat(HS1, HS2, gate_W, gate_U, W_gat, a_gat, adj, pool);

    // final head: FC1 via split-K partials + reduce(+tanh)
    zassemble_kernel<<<(N_NODES * G4 + 255) / 256, 256>>>(HS2, Z);
    {
        dim3 grid(9600 / XBN, (N_NODES + XBM - 1) / XBM, FC1_KS);
        fc1_partial_kernel<<<grid, 256>>>(Z, FC1, FCP);
        fc1_reduce_kernel<<<(int)((SZ_HC + 255) / 256), 256>>>(FCP, HC3);
    }
    rows_dot_kernel<1><<<N_NODES, 256>>>(HC3, 9600, FC2, 9600, BATT);
    {
        dim3 g((G4 + 255) / 256, CSCH);
        colsum_part_kernel<<<g, 256>>>(HS2, G4, N_NODES, nullptr, CSP, G4);
        colsum_red_kernel<<<(G4 + 255) / 256, 256>>>(CSP, 1.0f / (float)N_NODES, EA, G4);
        colsum_part_kernel<<<g, 256>>>(HS2, G4, N_NODES, BATT, CSP, G4);
        colsum_red_kernel<<<(G4 + 255) / 256, 256>>>(CSP, 1.0f, EA + G4, G4);
    }
    final_kernel<<<1, 256>>>(EA, Wlin, blin, out);
}